// round 3
// baseline (speedup 1.0000x reference)
#include <cuda_runtime.h>
#include <math.h>

#define B 64
#define L 512
#define H 1024
#define NREL 3
#define KSPLIT 4
#define MAT (NREL * B * H)      // 196608 floats per [3][64][1024] matrix

// Scratch (device globals — no allocation allowed)
__device__ float g_part[KSPLIT * MAT];    // split-K GEMM partials (reused 3x)
__device__ float g_hrel[MAT];             // tanh(concat @ W_rel)
__device__ float g_target[MAT];           // h_rel @ Win
__device__ float g_scores[NREL * B * L];  // scores -> probs (in place)
__device__ float g_wpart[KSPLIT * MAT];   // weighted-ctx L-split partials
__device__ float g_wctx[MAT];             // weighted context

// ---------------------------------------------------------------------------
// Generic split-K GEMM over A = concat(A1[64,1024], A2[64,1024]) (row-major,
// stride 1024), W row-major [(K1+K2), 1024]. Writes plain (non-atomic)
// partials: Cpart[split][rel][64][1024]. BM=64 (full batch), BN=64, BK=16.
// grid = (16 n-tiles, KSPLIT, 3 rels), block = 256.
// ---------------------------------------------------------------------------
__global__ __launch_bounds__(256) void gemm_concat_kernel(
    const float* __restrict__ A1_0, const float* __restrict__ A1_1, const float* __restrict__ A1_2,
    const float* __restrict__ A2_0, const float* __restrict__ A2_1, const float* __restrict__ A2_2,
    const float* __restrict__ W0,  const float* __restrict__ W1,  const float* __restrict__ W2,
    float* __restrict__ Cpart, int K1len, int kchunk)
{
    const int rel = blockIdx.z;
    const float* A1 = (rel == 0) ? A1_0 : (rel == 1) ? A1_1 : A1_2;
    const float* A2 = (rel == 0) ? A2_0 : (rel == 1) ? A2_1 : A2_2;
    const float* W  = (rel == 0) ? W0  : (rel == 1) ? W1  : W2;
    float* C = Cpart + (size_t)blockIdx.y * MAT + (size_t)rel * (B * H);

    const int n0   = blockIdx.x * 64;
    const int kbeg = blockIdx.y * kchunk;
    const int kend = kbeg + kchunk;

    __shared__ __align__(16) float As[16][64];
    __shared__ __align__(16) float Ws[16][64];

    const int tid = threadIdx.x;
    const int a_m = tid >> 2;            // 0..63
    const int a_k = (tid & 3) * 4;       // 0,4,8,12
    const int w_k = tid >> 4;            // 0..15
    const int w_n = (tid & 15) * 4;      // 0..60
    const int tx  = tid & 15;
    const int ty  = tid >> 4;

    float acc[4][4] = {};

    for (int k0 = kbeg; k0 < kend; k0 += 16) {
        // BK=16 tiles never straddle the concat boundary (K1len multiple of 16)
        const float* Aptr = (k0 < K1len)
            ? (A1 + (size_t)a_m * H + (k0 + a_k))
            : (A2 + (size_t)a_m * H + (k0 - K1len + a_k));
        float4 av = *(const float4*)Aptr;
        float4 wv = *(const float4*)(W + (size_t)(k0 + w_k) * H + n0 + w_n);
        __syncthreads();
        As[a_k + 0][a_m] = av.x;
        As[a_k + 1][a_m] = av.y;
        As[a_k + 2][a_m] = av.z;
        As[a_k + 3][a_m] = av.w;
        *(float4*)&Ws[w_k][w_n] = wv;
        __syncthreads();
        #pragma unroll
        for (int k = 0; k < 16; k++) {
            float4 a = *(const float4*)&As[k][ty * 4];
            float4 b = *(const float4*)&Ws[k][tx * 4];
            acc[0][0] += a.x * b.x; acc[0][1] += a.x * b.y; acc[0][2] += a.x * b.z; acc[0][3] += a.x * b.w;
            acc[1][0] += a.y * b.x; acc[1][1] += a.y * b.y; acc[1][2] += a.y * b.z; acc[1][3] += a.y * b.w;
            acc[2][0] += a.z * b.x; acc[2][1] += a.z * b.y; acc[2][2] += a.z * b.z; acc[2][3] += a.z * b.w;
            acc[3][0] += a.w * b.x; acc[3][1] += a.w * b.y; acc[3][2] += a.w * b.z; acc[3][3] += a.w * b.w;
        }
    }
    #pragma unroll
    for (int i = 0; i < 4; i++) {
        int m = ty * 4 + i;
        float4 v = make_float4(acc[i][0], acc[i][1], acc[i][2], acc[i][3]);
        *(float4*)(C + (size_t)m * H + n0 + tx * 4) = v;
    }
}

// Deterministic split-K reduction (+ optional tanh).
__global__ void reduce4_kernel(const float* __restrict__ in, float* __restrict__ outp, int do_tanh)
{
    int i = blockIdx.x * 256 + threadIdx.x;
    if (i >= MAT) return;
    float v = in[i] + in[MAT + i] + in[2 * MAT + i] + in[3 * MAT + i];
    outp[i] = do_tanh ? tanhf(v) : v;
}

// scores[rel][b][l] = dot(enc[b,l,:], target[rel][b,:]).  One warp per l-row,
// 8 rows per block. Targets cached in smem (12 KB). grid = (64 l-chunks, 64 b).
__global__ __launch_bounds__(256) void scores_kernel(
    const float* __restrict__ enc, const float* __restrict__ target, float* __restrict__ scores)
{
    const int b    = blockIdx.y;
    const int warp = threadIdx.x >> 5;
    const int lane = threadIdx.x & 31;
    const int l    = blockIdx.x * 8 + warp;

    __shared__ __align__(16) float st[3][H];
    for (int i = threadIdx.x; i < 3 * H; i += 256)
        st[i >> 10][i & 1023] = target[(size_t)((i >> 10) * B + b) * H + (i & 1023)];
    __syncthreads();

    const float4* erow = (const float4*)(enc + ((size_t)b * L + l) * H);
    float s0 = 0.f, s1 = 0.f, s2 = 0.f;
    #pragma unroll
    for (int i = 0; i < 8; i++) {
        int h4 = lane + i * 32;
        float4 e  = erow[h4];
        float4 t0 = *(const float4*)&st[0][h4 * 4];
        float4 t1 = *(const float4*)&st[1][h4 * 4];
        float4 t2 = *(const float4*)&st[2][h4 * 4];
        s0 += e.x * t0.x + e.y * t0.y + e.z * t0.z + e.w * t0.w;
        s1 += e.x * t1.x + e.y * t1.y + e.z * t1.z + e.w * t1.w;
        s2 += e.x * t2.x + e.y * t2.y + e.z * t2.z + e.w * t2.w;
    }
    #pragma unroll
    for (int o = 16; o > 0; o >>= 1) {
        s0 += __shfl_down_sync(0xffffffffu, s0, o);
        s1 += __shfl_down_sync(0xffffffffu, s1, o);
        s2 += __shfl_down_sync(0xffffffffu, s2, o);
    }
    if (lane == 0) {
        scores[(size_t)(0 * B + b) * L + l] = s0;
        scores[(size_t)(1 * B + b) * L + l] = s1;
        scores[(size_t)(2 * B + b) * L + l] = s2;
    }
}

// In-place softmax over L=512 for 192 rows, one warp per row (16 elems/lane).
__global__ void softmax_kernel(float* __restrict__ s)
{
    int row  = blockIdx.x * 8 + (threadIdx.x >> 5);
    int lane = threadIdx.x & 31;
    float* p = s + (size_t)row * L;
    float v[16];
    float mx = -1e30f;
    #pragma unroll
    for (int i = 0; i < 16; i++) { v[i] = p[lane + i * 32]; mx = fmaxf(mx, v[i]); }
    #pragma unroll
    for (int o = 16; o > 0; o >>= 1) mx = fmaxf(mx, __shfl_xor_sync(0xffffffffu, mx, o));
    float sum = 0.f;
    #pragma unroll
    for (int i = 0; i < 16; i++) { v[i] = __expf(v[i] - mx); sum += v[i]; }
    #pragma unroll
    for (int o = 16; o > 0; o >>= 1) sum += __shfl_xor_sync(0xffffffffu, sum, o);
    float inv = 1.f / sum;
    #pragma unroll
    for (int i = 0; i < 16; i++) p[lane + i * 32] = v[i] * inv;
}

// wpart[ls][rel][b][h] = sum over 128 l's of p[rel][b][l] * enc[b][l][h].
// grid = (4 l-splits, 64 b), block 256 (one float4 h-column per thread).
__global__ __launch_bounds__(256) void wctx_kernel(
    const float* __restrict__ enc, const float* __restrict__ probs, float* __restrict__ wpart)
{
    const int ls = blockIdx.x;
    const int b  = blockIdx.y;
    const int t  = threadIdx.x;

    __shared__ float sp[3][128];
    // 384 entries, 256 threads -> grid-stride (R2 bugfix: sp[2] was never filled)
    for (int i = t; i < 3 * 128; i += 256)
        sp[i >> 7][i & 127] = probs[(size_t)((i >> 7) * B + b) * L + ls * 128 + (i & 127)];
    __syncthreads();

    const float4* e = (const float4*)(enc + ((size_t)b * L + ls * 128) * H) + t;
    float4 a0 = {0,0,0,0}, a1 = {0,0,0,0}, a2 = {0,0,0,0};
    #pragma unroll 4
    for (int l = 0; l < 128; l++) {
        float4 ev = e[(size_t)l * 256];
        float p0 = sp[0][l], p1 = sp[1][l], p2 = sp[2][l];
        a0.x += p0 * ev.x; a0.y += p0 * ev.y; a0.z += p0 * ev.z; a0.w += p0 * ev.w;
        a1.x += p1 * ev.x; a1.y += p1 * ev.y; a1.z += p1 * ev.z; a1.w += p1 * ev.w;
        a2.x += p2 * ev.x; a2.y += p2 * ev.y; a2.z += p2 * ev.z; a2.w += p2 * ev.w;
    }
    float4* w = (float4*)(wpart + (size_t)ls * MAT);
    w[(size_t)(0 * B + b) * 256 + t] = a0;
    w[(size_t)(1 * B + b) * 256 + t] = a1;
    w[(size_t)(2 * B + b) * 256 + t] = a2;
}

// Sum final-GEMM split-K partials, tanh, broadcast F times to out[rel][b][f][h].
__global__ void bcast_kernel(const float* __restrict__ part, float* __restrict__ out, int F)
{
    int idx = blockIdx.x * 256 + threadIdx.x;      // 0..49151 float4 units
    const float4* p = (const float4*)part;
    const int S = MAT / 4;                         // 49152
    float4 v0 = p[idx], v1 = p[idx + S], v2 = p[idx + 2 * S], v3 = p[idx + 3 * S];
    float4 v;
    v.x = tanhf(v0.x + v1.x + v2.x + v3.x);
    v.y = tanhf(v0.y + v1.y + v2.y + v3.y);
    v.z = tanhf(v0.z + v1.z + v2.z + v3.z);
    v.w = tanhf(v0.w + v1.w + v2.w + v3.w);
    int rb = idx >> 8;                             // rel*64 + b
    int h4 = idx & 255;
    float4* o = (float4*)out + (size_t)rb * F * 256 + h4;
    for (int f = 0; f < F; f++) o[(size_t)f * 256] = v;
}

// ---------------------------------------------------------------------------
extern "C" void kernel_launch(void* const* d_in, const int* in_sizes, int n_in,
                              void* d_out, int out_size)
{
    const float* h_s     = (const float*)d_in[0];
    const float* h_o     = (const float*)d_in[1];
    const float* h_a     = (const float*)d_in[2];
    const float* enc     = (const float*)d_in[3];
    // d_in[4] = full_feature_len (derived from out_size instead)
    const float* W_as    = (const float*)d_in[5];
    const float* W_so    = (const float*)d_in[6];
    const float* W_oa    = (const float*)d_in[7];
    const float* Win_as  = (const float*)d_in[8];
    const float* Win_so  = (const float*)d_in[9];
    const float* Win_oa  = (const float*)d_in[10];
    const float* Wout_as = (const float*)d_in[11];
    const float* Wout_so = (const float*)d_in[12];
    const float* Wout_oa = (const float*)d_in[13];
    float* out = (float*)d_out;
    const int F = out_size / (NREL * B * H);       // 36

    float *p_part, *p_hrel, *p_target, *p_scores, *p_wpart, *p_wctx;
    cudaGetSymbolAddress((void**)&p_part,   g_part);
    cudaGetSymbolAddress((void**)&p_hrel,   g_hrel);
    cudaGetSymbolAddress((void**)&p_target, g_target);
    cudaGetSymbolAddress((void**)&p_scores, g_scores);
    cudaGetSymbolAddress((void**)&p_wpart,  g_wpart);
    cudaGetSymbolAddress((void**)&p_wctx,   g_wctx);

    const dim3 gg(16, KSPLIT, 3);

    // 1) h_rel = tanh(concat(h1,h2) @ W_rel)   [as: (a,s), so: (s,o), oa: (o,a)]
    gemm_concat_kernel<<<gg, 256>>>(h_a, h_s, h_o,   h_s, h_o, h_a,
                                    W_as, W_so, W_oa, p_part, H, 512);
    reduce4_kernel<<<768, 256>>>(p_part, p_hrel, 1);

    // 2) target = h_rel @ Win_rel
    gemm_concat_kernel<<<gg, 256>>>(p_hrel, p_hrel + B * H, p_hrel + 2 * B * H,
                                    p_hrel, p_hrel, p_hrel,   // unused (K2len side never hit)
                                    Win_as, Win_so, Win_oa, p_part, H, 256);
    reduce4_kernel<<<768, 256>>>(p_part, p_target, 0);

    // 3) scores = enc . target ; softmax ; weighted ctx
    scores_kernel<<<dim3(64, 64), 256>>>(enc, p_target, p_scores);
    softmax_kernel<<<24, 256>>>(p_scores);
    wctx_kernel<<<dim3(4, 64), 256>>>(enc, p_scores, p_wpart);
    reduce4_kernel<<<768, 256>>>(p_wpart, p_wctx, 0);

    // 4) h_final = tanh(concat(wctx, h_rel) @ Wout_rel), broadcast to out
    gemm_concat_kernel<<<gg, 256>>>(p_wctx, p_wctx + B * H, p_wctx + 2 * B * H,
                                    p_hrel, p_hrel + B * H, p_hrel + 2 * B * H,
                                    Wout_as, Wout_so, Wout_oa, p_part, H, 512);
    bcast_kernel<<<192, 256>>>(p_part, out, F);
}